// round 2
// baseline (speedup 1.0000x reference)
#include <cuda_runtime.h>
#include <cuda_fp16.h>
#include <cstdint>

// ============================================================================
// QuantLinear: out[M,N] = x[M,K] @ dequant(qweight, scales, qzeros)[K,N]
// M=8192, K=4096, N=11008, groupsize=128, 4-bit.
//
// The harness PTX target is compute_103 (no 'a' suffix) => tcgen05/TMEM are
// unavailable at the PTX level. Tensor path = mma.sync (HMMA), sm80-style
// cp.async multistage pipeline.
//
// Pass 1: x fp32 -> g_X fp16 [M,K] K-major
// Pass 2: dequant -> g_W fp16 [N,K] K-major (W^T)
// Pass 3: HMMA GEMM: CTA 128x128x64, 3 stages, 8 warps (2x4), warp 64x32.
// ============================================================================

constexpr int M = 8192;
constexpr int N = 11008;
constexpr int K = 4096;

constexpr int BM = 128;
constexpr int BN = 128;
constexpr int KC = 64;             // halves per stage = 128B rows (SW128)
constexpr int STAGES = 3;
constexpr int NK = K / KC;         // 64
constexpr int THREADS = 256;

constexpr int A_BYTES = BM * 128;            // 16384
constexpr int STAGE_BYTES = 2 * A_BYTES;     // 32768 (A then B)
constexpr int SMEM_BYTES = STAGES * STAGE_BYTES;  // 98304 -> 2 CTAs/SM

static_assert(M % BM == 0 && N % BN == 0 && K % KC == 0, "exact tiling");

__device__ __half g_X[(size_t)M * K];   // [M, K]
__device__ __half g_W[(size_t)N * K];   // [N, K] (i.e. W^T), K-major

// ----------------------------------------------------------------------------
// helpers
// ----------------------------------------------------------------------------
__device__ __forceinline__ void cp16(uint32_t smem_dst, const void* gsrc) {
    asm volatile("cp.async.cg.shared.global [%0], [%1], 16;"
                 :: "r"(smem_dst), "l"(gsrc));
}

__device__ __forceinline__ void ldsm4(uint32_t* r, uint32_t addr) {
    asm volatile("ldmatrix.sync.aligned.m8n8.x4.shared.b16 {%0,%1,%2,%3}, [%4];"
                 : "=r"(r[0]), "=r"(r[1]), "=r"(r[2]), "=r"(r[3]) : "r"(addr));
}

__device__ __forceinline__ void mma16816(float* c, const uint32_t* a, const uint32_t* b) {
    asm volatile(
        "mma.sync.aligned.m16n8k16.row.col.f32.f16.f16.f32 "
        "{%0,%1,%2,%3}, {%4,%5,%6,%7}, {%8,%9}, {%0,%1,%2,%3};"
        : "+f"(c[0]), "+f"(c[1]), "+f"(c[2]), "+f"(c[3])
        : "r"(a[0]), "r"(a[1]), "r"(a[2]), "r"(a[3]), "r"(b[0]), "r"(b[1]));
}

// Load one stage: A tile (128 rows x 128B) + B tile (128 rows x 128B), SW128.
// Row r, 16B chunk c stored at r*128 + ((c ^ (r&7))*16).
__device__ __forceinline__ void load_stage(uint32_t sbase, int slot, int kt,
                                           const __half* Ag, const __half* Bg,
                                           int tid) {
    const uint32_t a_s = sbase + slot * STAGE_BYTES;
    const uint32_t b_s = a_s + A_BYTES;
    const __half* Ak = Ag + kt * KC;
    const __half* Bk = Bg + kt * KC;
#pragma unroll
    for (int it = 0; it < 4; it++) {        // 128 rows * 8 chunks / 256 threads
        int idx = tid + it * THREADS;
        int r = idx >> 3, c = idx & 7;
        uint32_t off = (uint32_t)r * 128 + (uint32_t)((c ^ (r & 7)) * 16);
        cp16(a_s + off, Ak + (size_t)r * K + c * 8);
        cp16(b_s + off, Bk + (size_t)r * K + c * 8);
    }
}

// ----------------------------------------------------------------------------
// Pass 1: x fp32 -> fp16
// ----------------------------------------------------------------------------
__global__ void __launch_bounds__(256)
convert_x_kernel(const float* __restrict__ x) {
    int idx = blockIdx.x * 256 + threadIdx.x;      // over M*K/4 (exact)
    float4 v = ((const float4*)x)[idx];
    __half2 h0 = __floats2half2_rn(v.x, v.y);
    __half2 h1 = __floats2half2_rn(v.z, v.w);
    uint2 o;
    o.x = *(unsigned*)&h0;
    o.y = *(unsigned*)&h1;
    ((uint2*)g_X)[idx] = o;
}

// ----------------------------------------------------------------------------
// Pass 2: dequant. One thread per qweight int32 (8 K-values at one n).
// k = r*8 + j (shift j), group g = r>>4. zero(n) = (qzeros[g][n/8] >> 4*(n%8)) & 0xF
// ----------------------------------------------------------------------------
__global__ void __launch_bounds__(256)
dequant_kernel(const int* __restrict__ qweight, const float* __restrict__ scales,
               const int* __restrict__ qzeros) {
    int idx = blockIdx.x * 256 + threadIdx.x;      // over (K/8)*N (exact)
    int n = idx % N;
    int r = idx / N;
    int g = r >> 4;
    unsigned q  = ((const unsigned*)qweight)[idx];
    unsigned qz = ((const unsigned*)qzeros)[g * (N / 8) + (n >> 3)];
    float z = (float)((qz >> ((n & 7) * 4)) & 0xF);
    float s = scales[g * N + n];
    __half2 outv[4];
#pragma unroll
    for (int j = 0; j < 4; j++) {
        float v0 = s * ((float)((q >> (8 * j))     & 0xF) - z);
        float v1 = s * ((float)((q >> (8 * j + 4)) & 0xF) - z);
        outv[j] = __floats2half2_rn(v0, v1);
    }
    *(uint4*)&g_W[(size_t)n * K + r * 8] = *(uint4*)outv;
}

// ----------------------------------------------------------------------------
// Pass 3: GEMM
// ----------------------------------------------------------------------------
__global__ void __launch_bounds__(THREADS, 2)
gemm_kernel(float* __restrict__ out) {
    extern __shared__ char smem[];
    const uint32_t sbase = (uint32_t)__cvta_generic_to_shared(smem);
    const int tid  = threadIdx.x;
    const int warp = tid >> 5;
    const int lane = tid & 31;
    const int wm = warp & 1;          // 2 warps in M
    const int wn = warp >> 1;         // 4 warps in N
    const int m0 = blockIdx.x * BM;
    const int n0 = blockIdx.y * BN;

    const __half* Ag = g_X + (size_t)m0 * K;
    const __half* Bg = g_W + (size_t)n0 * K;

    float acc[4][4][4];
#pragma unroll
    for (int i = 0; i < 4; i++)
#pragma unroll
        for (int j = 0; j < 4; j++)
#pragma unroll
            for (int e = 0; e < 4; e++) acc[i][j][e] = 0.f;

    // ldmatrix address components (canonical x4 tile ordering):
    // A frag (m16k16): lanes 0-7 rows m0..7/kc0, 8-15 rows m8..15/kc0,
    //                  16-23 rows m0..7/kc1, 24-31 rows m8..15/kc1.
    const int arow = wm * 64 + (lane & 15);
    const int asel = lane >> 4;              // +0/+1 k-chunk
    // B frags (2x n8k16 per x4): lanes 0-7 n0..7/kc0, 8-15 n0..7/kc1,
    //                            16-23 n8..15/kc0, 24-31 n8..15/kc1.
    const int brow = wn * 32 + (((lane >> 4) & 1) << 3) + (lane & 7);
    const int bsel = (lane >> 3) & 1;

    // prologue
    load_stage(sbase, 0, 0, Ag, Bg, tid);
    asm volatile("cp.async.commit_group;" ::: "memory");
    load_stage(sbase, 1, 1, Ag, Bg, tid);
    asm volatile("cp.async.commit_group;" ::: "memory");

    int slot = 0;
    for (int i = 0; i < NK; i++) {
        asm volatile("cp.async.wait_group 1;" ::: "memory");
        __syncthreads();     // stage i visible to all; prev compute done before reload

        if (i + 2 < NK) {
            int ns = slot - 1; if (ns < 0) ns += STAGES;   // (i+2) % 3
            load_stage(sbase, ns, i + 2, Ag, Bg, tid);
        }
        asm volatile("cp.async.commit_group;" ::: "memory");

        const uint32_t a_s = sbase + slot * STAGE_BYTES;
        const uint32_t b_s = a_s + A_BYTES;
#pragma unroll
        for (int ks = 0; ks < KC / 16; ks++) {
            uint32_t a[4][4], b[2][4];
#pragma unroll
            for (int mf = 0; mf < 4; mf++) {
                int row = arow + mf * 16;
                int kc  = ks * 2 + asel;
                ldsm4(a[mf], a_s + row * 128 + ((kc ^ (row & 7)) * 16));
            }
#pragma unroll
            for (int nf2 = 0; nf2 < 2; nf2++) {
                int row = brow + nf2 * 16;
                int kc  = ks * 2 + bsel;
                ldsm4(b[nf2], b_s + row * 128 + ((kc ^ (row & 7)) * 16));
            }
#pragma unroll
            for (int mf = 0; mf < 4; mf++)
#pragma unroll
                for (int nf = 0; nf < 4; nf++)
                    mma16816(acc[mf][nf], a[mf], &b[nf >> 1][(nf & 1) * 2]);
        }
        slot++; if (slot == STAGES) slot = 0;
    }

    // Epilogue: direct register -> gmem (32B-coalesced float2 stores)
    const int mbase = m0 + wm * 64 + (lane >> 2);
    const int nbase = n0 + wn * 32 + (lane & 3) * 2;
#pragma unroll
    for (int mf = 0; mf < 4; mf++)
#pragma unroll
        for (int nf = 0; nf < 4; nf++) {
            float* p0 = &out[(size_t)(mbase + mf * 16)     * N + nbase + nf * 8];
            float* p1 = &out[(size_t)(mbase + mf * 16 + 8) * N + nbase + nf * 8];
            *(float2*)p0 = make_float2(acc[mf][nf][0], acc[mf][nf][1]);
            *(float2*)p1 = make_float2(acc[mf][nf][2], acc[mf][nf][3]);
        }
}

// ----------------------------------------------------------------------------
extern "C" void kernel_launch(void* const* d_in, const int* in_sizes, int n_in,
                              void* d_out, int out_size) {
    (void)in_sizes; (void)n_in; (void)out_size;
    const float* x       = (const float*)d_in[0];
    const int*   qweight = (const int*)d_in[1];
    const float* scales  = (const float*)d_in[2];
    const int*   qzeros  = (const int*)d_in[3];
    float* out = (float*)d_out;

    convert_x_kernel<<<(M * K / 4) / 256, 256>>>(x);
    dequant_kernel<<<((K / 8) * N) / 256, 256>>>(qweight, scales, qzeros);

    cudaFuncSetAttribute(gemm_kernel, cudaFuncAttributeMaxDynamicSharedMemorySize,
                         SMEM_BYTES);
    dim3 grid(M / BM, N / BN);   // (64, 86); x fast -> wave shares B tiles in L2
    gemm_kernel<<<grid, THREADS, SMEM_BYTES>>>(out);
}